// round 3
// baseline (speedup 1.0000x reference)
#include <cuda_runtime.h>
#include <math.h>

#define NN 8192
#define KK 32
#define DD 64
#define DID 32
#define BSZ 4
#define TT 8
#define DSCAN 1024

#define NT 8            // nodes per block
#define ROWS 32         // NT * BSZ rows per block
#define RP 34           // transposed-buffer row pitch (even, conflict-spread)

typedef unsigned long long ull;

// Persistent state (allocation-free scratch)
__device__ float g_h[BSZ * NN * DD];
__device__ float g_msgs[2][BSZ * NN * DD];
__device__ float g_wc[BSZ * NN * KK];
__device__ float g_ident[NN * DID];
// Duplicated ({w,w} packed pairs) weight matrices
__device__ float g_dw1d[256 * 512];
__device__ float g_sw1d[224 * 512];
__device__ float g_mw1d[96 * 512];
__device__ float g_dw2d[256 * 256];   // dw2 padded 65->128 cols, dup'd
__device__ float g_sw2d[256 * 128];
__device__ float g_mw2d[256 * 128];
__device__ float g_db2p[128];

__device__ __forceinline__ float sigf(float x) { return 1.0f / (1.0f + __expf(-x)); }

__device__ __forceinline__ ull ffma2(ull a, ull b, ull c) {
    ull d;
    asm("fma.rn.f32x2 %0, %1, %2, %3;" : "=l"(d) : "l"(a), "l"(b), "l"(c));
    return d;
}
__device__ __forceinline__ float2 unpack2(ull p) {
    unsigned lo, hi;
    asm("mov.b64 {%0, %1}, %2;" : "=r"(lo), "=r"(hi) : "l"(p));
    return make_float2(__uint_as_float(lo), __uint_as_float(hi));
}
__device__ __forceinline__ ull repack(float x, float y) {
    ull p;
    unsigned a = __float_as_uint(x), b = __float_as_uint(y);
    asm("mov.b64 %0, {%1, %2};" : "=l"(p) : "r"(a), "r"(b));
    return p;
}

// Yt[yoff+c][r] = act(sum_k Xt[k][r] * W[k][c] + b[c]).
// Xt transposed in smem (pitch RP). Wd is the duplicated weight matrix (row len 2*COLS).
// 8 warps split COLS; lane = 4 row-groups x 8 col-groups; rows packed in f32x2.
// ACT: 0 = none, 1 = silu, 2 = tanh
template <int CPT, int ACT, int CIN, int COLS>
__device__ __forceinline__ void gemmT(const float* Xt,
                                      const float* __restrict__ Wd,
                                      const float* __restrict__ bias,
                                      float* Yt, int yoff) {
    const int w = threadIdx.x >> 5;
    const int lane = threadIdx.x & 31;
    const int rg = lane >> 3;
    const int cg = lane & 7;
    const int r0 = rg * 8;
    const int c0 = w * (COLS / 8) + cg * CPT;
    ull acc[4][CPT];
#pragma unroll
    for (int p = 0; p < 4; p++)
#pragma unroll
        for (int j = 0; j < CPT; j++) acc[p][j] = 0ull;

    const float* xb = Xt + r0;
    const float* wb = Wd + 2 * c0;
#pragma unroll 4
    for (int k = 0; k < CIN; k++) {
        ull xp[4];
#pragma unroll
        for (int p = 0; p < 4; p++)
            xp[p] = *reinterpret_cast<const ull*>(xb + k * RP + 2 * p);
        ull wv[CPT];
        const float* wr = wb + (size_t)k * (2 * COLS);
        if (CPT == 4) {
            ulonglong2 a = __ldg(reinterpret_cast<const ulonglong2*>(wr));
            ulonglong2 b = __ldg(reinterpret_cast<const ulonglong2*>(wr) + 1);
            wv[0] = a.x; wv[1] = a.y; wv[2] = b.x; wv[3] = b.y;
        } else if (CPT == 2) {
            ulonglong2 a = __ldg(reinterpret_cast<const ulonglong2*>(wr));
            wv[0] = a.x; wv[1] = a.y;
        } else {
            wv[0] = __ldg(reinterpret_cast<const ull*>(wr));
        }
#pragma unroll
        for (int p = 0; p < 4; p++)
#pragma unroll
            for (int j = 0; j < CPT; j++)
                acc[p][j] = ffma2(xp[p], wv[j], acc[p][j]);
    }
#pragma unroll
    for (int j = 0; j < CPT; j++) {
        float bc = __ldg(bias + c0 + j);
#pragma unroll
        for (int p = 0; p < 4; p++) {
            float2 v = unpack2(acc[p][j]);
            v.x += bc; v.y += bc;
            if (ACT == 1) {
                v.x = v.x * (1.0f / (1.0f + __expf(-v.x)));
                v.y = v.y * (1.0f / (1.0f + __expf(-v.y)));
            } else if (ACT == 2) {
                v.x = tanhf(v.x);
                v.y = tanhf(v.y);
            }
            *reinterpret_cast<ull*>(Yt + (yoff + c0 + j) * RP + r0 + 2 * p) =
                repack(v.x, v.y);
        }
    }
}

__global__ void __launch_bounds__(256, 2) step_kernel(
    const float* __restrict__ cc, const float* __restrict__ hebb,
    const int* __restrict__ conn,
    const float* __restrict__ sb1, const float* __restrict__ sb2,
    const float* __restrict__ mb1, const float* __restrict__ mb2,
    const float* __restrict__ db1,
    float* __restrict__ out, int t, int p) {
    extern __shared__ float sm[];
    float* A = sm;                     // 256*RP transposed (mod_in / scratch)
    float* B = A + 256 * RP;           // 256*RP (hidden / state_in / msg_in)
    float* C = B + 256 * RP;           // 256*RP (mod_out / hidden)
    float* wk = C + 256 * RP;          // ROWS*KK sigmoid(w_conn)
    float* idn = wk + ROWS * KK;       // NT*DID new identity
    float* dec = idn + NT * DID;       // ROWS decay
    int* idxs = (int*)(dec + ROWS);    // NT*KK neighbor indices

    const int tid = threadIdx.x;
    const int n0 = blockIdx.x * NT;

    // ---- Phase 0: indices + sigmoid(w_conn) + transposed mod_in fills ----
    {
        int ln = tid >> 5, k = tid & 31;
        idxs[tid] = conn[(n0 + ln) * KK + k];
    }
    for (int i = tid; i < ROWS * KK; i += 256) {
        int r = i >> 5, k = i & 31, ln = r >> 2, b = r & 3;
        wk[i] = sigf(g_wc[((size_t)b * NN + n0 + ln) * KK + k]);
    }
    for (int i = tid; i < ROWS * KK; i += 256) {  // hebbian -> rows [0:32]
        int r = i >> 5, j = i & 31, ln = r >> 2, b = r & 3;
        A[j * RP + r] = hebb[((size_t)b * NN + n0 + ln) * KK + j];
    }
    for (int i = tid; i < ROWS * DD; i += 256) {  // h -> [32:96]
        int r = i >> 6, d = i & 63, ln = r >> 2, b = r & 3;
        A[(32 + d) * RP + r] = g_h[((size_t)b * NN + n0 + ln) * DD + d];
    }
    for (int i = tid; i < ROWS * DID; i += 256) {  // ident -> [96:128]
        int r = i >> 5, j = i & 31, ln = r >> 2;
        A[(96 + j) * RP + r] = g_ident[(n0 + ln) * DID + j];
    }
    for (int i = tid; i < ROWS * DD; i += 256) {  // inject -> [192:256]
        int r = i >> 6, d = i & 63, ln = r >> 2, b = r & 3;
        int n = n0 + ln;
        A[(192 + d) * RP + r] = cc[((size_t)b * TT + t) * DSCAN + (n >> 9) * DD + d];
    }
    __syncthreads();

    // ---- received = sum_k sigmoid(w) * msgs[neighbor] -> rows [128:192] ----
    {
        const int sub = tid >> 6;  // batch index
        const int d = tid & 63;
        const float* mp = g_msgs[p];
        for (int it = 0; it < NT; it++) {
            int r = it * 4 + sub;
            float acc = 0.0f;
#pragma unroll 8
            for (int k = 0; k < KK; k++) {
                int nb = idxs[it * KK + k];
                acc = fmaf(wk[r * KK + k], mp[((size_t)sub * NN + nb) * DD + d], acc);
            }
            A[(128 + d) * RP + r] = acc;
        }
    }
    __syncthreads();

    // ---- mod MLP ----
    gemmT<4, 1, 256, 256>(A, g_dw1d, db1, B, 0);
    __syncthreads();
    gemmT<2, 0, 256, 128>(B, g_dw2d, g_db2p, C, 0);
    __syncthreads();

    // ---- w_new, decay, identity update (batch mean) ----
    for (int i = tid; i < ROWS * KK; i += 256) {
        int r = i >> 5, k = i & 31, ln = r >> 2, b = r & 3;
        g_wc[((size_t)b * NN + n0 + ln) * KK + k] = C[k * RP + r];
    }
    if (tid < ROWS) dec[tid] = sigf(C[32 * RP + tid]);
    {
        int ln = tid >> 5, j = tid & 31;
        const float* cr = C + (33 + j) * RP + ln * 4;
        float v = g_ident[(n0 + ln) * DID + j] +
                  0.25f * (cr[0] + cr[1] + cr[2] + cr[3]);
        idn[tid] = v;
        g_ident[(n0 + ln) * DID + j] = v;
    }
    __syncthreads();

    // ---- build state_in rows: [received, inject, h, ide2] into B ----
    for (int i = tid; i < 224 * 16; i += 256) {  // float2 over r
        int c = i >> 4, m = i & 15;
        int src;
        if (c < 64) src = 128 + c;
        else if (c < 128) src = 192 + (c - 64);
        else if (c < 192) src = 32 + (c - 128);
        else src = -1;
        float2 v;
        if (src >= 0) {
            v = *reinterpret_cast<const float2*>(A + src * RP + 2 * m);
        } else {
            int j = c - 192;
            int r = 2 * m;
            v.x = idn[(r >> 2) * DID + j];
            v.y = idn[((r + 1) >> 2) * DID + j];
        }
        *reinterpret_cast<float2*>(B + c * RP + 2 * m) = v;
    }
    __syncthreads();

    // ---- state MLP ----
    gemmT<4, 1, 224, 256>(B, g_sw1d, sb1, C, 0);
    __syncthreads();
    gemmT<1, 2, 256, 64>(C, g_sw2d, sb2, A, 96);  // tanh -> A rows [96:160]
    __syncthreads();

    // ---- h_new = decay*h + (1-decay)*tanh; write out + msg input ----
    for (int i = tid; i < ROWS * DD; i += 256) {
        int r = i >> 6, d = i & 63, ln = r >> 2, b = r & 3;
        float de = dec[r];
        float hn = de * A[(32 + d) * RP + r] + (1.0f - de) * A[(96 + d) * RP + r];
        g_h[((size_t)b * NN + n0 + ln) * DD + d] = hn;
        out[(((size_t)b * TT + t) * NN + n0 + ln) * DD + d] = hn;
        B[d * RP + r] = hn;
    }
    for (int i = tid; i < ROWS * DID; i += 256) {
        int r = i >> 5, j = i & 31;
        B[(64 + j) * RP + r] = idn[(r >> 2) * DID + j];
    }
    __syncthreads();

    // ---- msg MLP ----
    gemmT<4, 1, 96, 256>(B, g_mw1d, mb1, C, 0);
    __syncthreads();
    gemmT<1, 2, 256, 64>(C, g_mw2d, mb2, A, 0);  // tanh -> A rows [0:64]
    __syncthreads();
    for (int i = tid; i < ROWS * DD; i += 256) {
        int r = i >> 6, d = i & 63, ln = r >> 2, b = r & 3;
        g_msgs[p ^ 1][((size_t)b * NN + n0 + ln) * DD + d] = A[d * RP + r];
    }
}

__global__ void init_kernel(const float* __restrict__ h0, const float* __restrict__ m0,
                            const float* __restrict__ w0, const float* __restrict__ id0,
                            const float* __restrict__ dw1, const float* __restrict__ sw1,
                            const float* __restrict__ mw1, const float* __restrict__ dw2,
                            const float* __restrict__ sw2, const float* __restrict__ mw2,
                            const float* __restrict__ db2) {
    size_t i = (size_t)blockIdx.x * blockDim.x + threadIdx.x;
    if (i < (size_t)BSZ * NN * DD) {
        g_h[i] = h0[i];
        g_msgs[0][i] = m0[i];
    }
    if (i < (size_t)BSZ * NN * KK) g_wc[i] = w0[i];
    if (i < (size_t)NN * DID) g_ident[i] = id0[i];
    if (i < 256 * 256) {
        int r = (int)i >> 8, c = (int)i & 255;
        float v = dw1[i];
        g_dw1d[r * 512 + 2 * c] = v;
        g_dw1d[r * 512 + 2 * c + 1] = v;
    }
    if (i < 224 * 256) {
        int r = (int)i >> 8, c = (int)i & 255;
        float v = sw1[i];
        g_sw1d[r * 512 + 2 * c] = v;
        g_sw1d[r * 512 + 2 * c + 1] = v;
    }
    if (i < 96 * 256) {
        int r = (int)i >> 8, c = (int)i & 255;
        float v = mw1[i];
        g_mw1d[r * 512 + 2 * c] = v;
        g_mw1d[r * 512 + 2 * c + 1] = v;
    }
    if (i < 256 * 128) {
        int r = (int)i >> 7, c = (int)i & 127;
        float v = (c < 65) ? dw2[r * 65 + c] : 0.0f;
        g_dw2d[r * 256 + 2 * c] = v;
        g_dw2d[r * 256 + 2 * c + 1] = v;
    }
    if (i < 256 * 64) {
        int r = (int)i >> 6, c = (int)i & 63;
        float v = sw2[i];
        g_sw2d[r * 128 + 2 * c] = v;
        g_sw2d[r * 128 + 2 * c + 1] = v;
        float v2 = mw2[i];
        g_mw2d[r * 128 + 2 * c] = v2;
        g_mw2d[r * 128 + 2 * c + 1] = v2;
    }
    if (i < 128) g_db2p[i] = (i < 65) ? db2[i] : 0.0f;
}

#define SMEM_BYTES ((3 * 256 * RP + ROWS * KK + NT * DID + ROWS) * 4 + NT * KK * 4)

extern "C" void kernel_launch(void* const* d_in, const int* in_sizes, int n_in,
                              void* d_out, int out_size) {
    const float* cc   = (const float*)d_in[0];
    const float* h0   = (const float*)d_in[1];
    const float* m0   = (const float*)d_in[2];
    const float* w0   = (const float*)d_in[3];
    const float* hebb = (const float*)d_in[4];
    const float* id0  = (const float*)d_in[5];
    const float* sw1  = (const float*)d_in[6];
    const float* sb1  = (const float*)d_in[7];
    const float* sw2  = (const float*)d_in[8];
    const float* sb2  = (const float*)d_in[9];
    const float* mw1  = (const float*)d_in[10];
    const float* mb1  = (const float*)d_in[11];
    const float* mw2  = (const float*)d_in[12];
    const float* mb2  = (const float*)d_in[13];
    const float* dw1  = (const float*)d_in[14];
    const float* db1  = (const float*)d_in[15];
    const float* dw2  = (const float*)d_in[16];
    const float* db2  = (const float*)d_in[17];
    const int* conn   = (const int*)d_in[18];
    float* out = (float*)d_out;

    cudaFuncSetAttribute(step_kernel, cudaFuncAttributeMaxDynamicSharedMemorySize,
                         SMEM_BYTES);

    init_kernel<<<(BSZ * NN * DD + 255) / 256, 256>>>(h0, m0, w0, id0, dw1, sw1, mw1,
                                                      dw2, sw2, mw2, db2);
    for (int t = 0; t < TT; t++) {
        step_kernel<<<NN / NT, 256, SMEM_BYTES>>>(
            cc, hebb, conn, sb1, sb2, mb1, mb2, db1, out, t, t & 1);
    }
}

// round 4
// speedup vs baseline: 1.3128x; 1.3128x over previous
#include <cuda_runtime.h>
#include <math.h>

#define NN 8192
#define KK 32
#define DD 64
#define DID 32
#define BSZ 4
#define TT 8
#define DSCAN 1024

#define NT 8            // nodes per block
#define ROWS 32         // NT * BSZ rows per block
#define RP 34           // transposed-buffer row pitch (even, conflict-spread)

typedef unsigned long long ull;

// Persistent state (allocation-free scratch)
__device__ float g_h[BSZ * NN * DD];
__device__ float g_msgs[2][BSZ * NN * DD];
__device__ float g_wc[BSZ * NN * KK];
__device__ float g_ident[NN * DID];
__device__ float g_dw2p[256 * 128];   // dw2 padded 65 -> 128 cols
__device__ float g_db2p[128];

__device__ __forceinline__ float sigf(float x) { return 1.0f / (1.0f + __expf(-x)); }

__device__ __forceinline__ ull ffma2(ull a, ull b, ull c) {
    ull d;
    asm("fma.rn.f32x2 %0, %1, %2, %3;" : "=l"(d) : "l"(a), "l"(b), "l"(c));
    return d;
}
__device__ __forceinline__ ull pack2(float x) {
    ull p;
    unsigned u = __float_as_uint(x);
    asm("mov.b64 %0, {%1, %2};" : "=l"(p) : "r"(u), "r"(u));
    return p;
}
__device__ __forceinline__ float2 unpack2(ull p) {
    unsigned lo, hi;
    asm("mov.b64 {%0, %1}, %2;" : "=r"(lo), "=r"(hi) : "l"(p));
    return make_float2(__uint_as_float(lo), __uint_as_float(hi));
}
__device__ __forceinline__ ull repack(float x, float y) {
    ull p;
    unsigned a = __float_as_uint(x), b = __float_as_uint(y);
    asm("mov.b64 %0, {%1, %2};" : "=l"(p) : "r"(a), "r"(b));
    return p;
}

// Yt[yoff+c][r] = act(sum_k Xt[k][r] * W[k][c] + b[c]).
// Xt transposed in smem (pitch RP). W plain row-major [CIN x COLS].
// 8 warps split COLS; lane = 4 row-groups x 8 col-groups; rows packed in f32x2.
// W loaded dense (LDG.128/64/32), splatted to {w,w} via ALU mov.b64.
// ACT: 0 = none, 1 = silu, 2 = tanh
template <int CPT, int ACT, int CIN, int COLS>
__device__ __forceinline__ void gemmT(const float* Xt,
                                      const float* __restrict__ W,
                                      const float* __restrict__ bias,
                                      float* Yt, int yoff) {
    const int w = threadIdx.x >> 5;
    const int lane = threadIdx.x & 31;
    const int rg = lane >> 3;
    const int cg = lane & 7;
    const int r0 = rg * 8;
    const int c0 = w * (COLS / 8) + cg * CPT;
    ull acc[4][CPT];
#pragma unroll
    for (int p = 0; p < 4; p++)
#pragma unroll
        for (int j = 0; j < CPT; j++) acc[p][j] = 0ull;

    const float* xb = Xt + r0;
    const float* wb = W + c0;
#pragma unroll 4
    for (int k = 0; k < CIN; k++) {
        ull xp[4];
#pragma unroll
        for (int p = 0; p < 4; p++)
            xp[p] = *reinterpret_cast<const ull*>(xb + k * RP + 2 * p);
        float wv[CPT];
        const float* wr = wb + (size_t)k * COLS;
        if (CPT == 4) {
            float4 f = __ldg(reinterpret_cast<const float4*>(wr));
            wv[0] = f.x; wv[1] = f.y; wv[2] = f.z; wv[3] = f.w;
        } else if (CPT == 2) {
            float2 f = __ldg(reinterpret_cast<const float2*>(wr));
            wv[0] = f.x; wv[1] = f.y;
        } else {
            wv[0] = __ldg(wr);
        }
        ull wp[CPT];
#pragma unroll
        for (int j = 0; j < CPT; j++) wp[j] = pack2(wv[j]);
#pragma unroll
        for (int p = 0; p < 4; p++)
#pragma unroll
            for (int j = 0; j < CPT; j++)
                acc[p][j] = ffma2(xp[p], wp[j], acc[p][j]);
    }
#pragma unroll
    for (int j = 0; j < CPT; j++) {
        float bc = __ldg(bias + c0 + j);
#pragma unroll
        for (int p = 0; p < 4; p++) {
            float2 v = unpack2(acc[p][j]);
            v.x += bc; v.y += bc;
            if (ACT == 1) {
                v.x = v.x * (1.0f / (1.0f + __expf(-v.x)));
                v.y = v.y * (1.0f / (1.0f + __expf(-v.y)));
            } else if (ACT == 2) {
                v.x = tanhf(v.x);
                v.y = tanhf(v.y);
            }
            *reinterpret_cast<ull*>(Yt + (yoff + c0 + j) * RP + r0 + 2 * p) =
                repack(v.x, v.y);
        }
    }
}

__global__ void __launch_bounds__(256, 2) step_kernel(
    const float* __restrict__ cc, const float* __restrict__ hebb,
    const int* __restrict__ conn,
    const float* __restrict__ sw1, const float* __restrict__ sb1,
    const float* __restrict__ sw2, const float* __restrict__ sb2,
    const float* __restrict__ mw1, const float* __restrict__ mb1,
    const float* __restrict__ mw2, const float* __restrict__ mb2,
    const float* __restrict__ dw1, const float* __restrict__ db1,
    float* __restrict__ out, int t, int p) {
    extern __shared__ float sm[];
    float* A = sm;                     // 256*RP transposed (mod_in / scratch)
    float* B = A + 256 * RP;           // 256*RP (hidden / state_in / msg_in)
    float* C = B + 256 * RP;           // 256*RP (mod_out / hidden)
    float* wk = C + 256 * RP;          // ROWS*KK sigmoid(w_conn)
    float* idn = wk + ROWS * KK;       // NT*DID new identity
    float* dec = idn + NT * DID;       // ROWS decay
    int* idxs = (int*)(dec + ROWS);    // NT*KK neighbor indices

    const int tid = threadIdx.x;
    const int n0 = blockIdx.x * NT;

    // ---- Phase 0: indices + sigmoid(w_conn) + transposed mod_in fills ----
    {
        int ln = tid >> 5, k = tid & 31;
        idxs[tid] = conn[(n0 + ln) * KK + k];
    }
    for (int i = tid; i < ROWS * KK; i += 256) {
        int r = i >> 5, k = i & 31, ln = r >> 2, b = r & 3;
        wk[i] = sigf(g_wc[((size_t)b * NN + n0 + ln) * KK + k]);
    }
    for (int i = tid; i < ROWS * KK; i += 256) {  // hebbian -> rows [0:32]
        int r = i >> 5, j = i & 31, ln = r >> 2, b = r & 3;
        A[j * RP + r] = hebb[((size_t)b * NN + n0 + ln) * KK + j];
    }
    for (int i = tid; i < ROWS * DD; i += 256) {  // h -> [32:96]
        int r = i >> 6, d = i & 63, ln = r >> 2, b = r & 3;
        A[(32 + d) * RP + r] = g_h[((size_t)b * NN + n0 + ln) * DD + d];
    }
    for (int i = tid; i < ROWS * DID; i += 256) {  // ident -> [96:128]
        int r = i >> 5, j = i & 31, ln = r >> 2;
        A[(96 + j) * RP + r] = g_ident[(n0 + ln) * DID + j];
    }
    for (int i = tid; i < ROWS * DD; i += 256) {  // inject -> [192:256]
        int r = i >> 6, d = i & 63, ln = r >> 2, b = r & 3;
        int n = n0 + ln;
        A[(192 + d) * RP + r] = cc[((size_t)b * TT + t) * DSCAN + (n >> 9) * DD + d];
    }
    __syncthreads();

    // ---- received = sum_k sigmoid(w) * msgs[neighbor] -> rows [128:192] ----
    {
        const int sub = tid >> 6;  // batch index
        const int d = tid & 63;
        const float* mp = g_msgs[p];
        for (int it = 0; it < NT; it++) {
            int r = it * 4 + sub;
            float acc = 0.0f;
#pragma unroll 8
            for (int k = 0; k < KK; k++) {
                int nb = idxs[it * KK + k];
                acc = fmaf(wk[r * KK + k], mp[((size_t)sub * NN + nb) * DD + d], acc);
            }
            A[(128 + d) * RP + r] = acc;
        }
    }
    __syncthreads();

    // ---- mod MLP ----
    gemmT<4, 1, 256, 256>(A, dw1, db1, B, 0);
    __syncthreads();
    gemmT<2, 0, 256, 128>(B, g_dw2p, g_db2p, C, 0);
    __syncthreads();

    // ---- w_new, decay, identity update (batch mean) ----
    for (int i = tid; i < ROWS * KK; i += 256) {
        int r = i >> 5, k = i & 31, ln = r >> 2, b = r & 3;
        g_wc[((size_t)b * NN + n0 + ln) * KK + k] = C[k * RP + r];
    }
    if (tid < ROWS) dec[tid] = sigf(C[32 * RP + tid]);
    {
        int ln = tid >> 5, j = tid & 31;
        const float* cr = C + (33 + j) * RP + ln * 4;
        float v = g_ident[(n0 + ln) * DID + j] +
                  0.25f * (cr[0] + cr[1] + cr[2] + cr[3]);
        idn[tid] = v;
        g_ident[(n0 + ln) * DID + j] = v;
    }
    __syncthreads();

    // ---- build state_in rows: [received, inject, h, ide2] into B ----
    for (int i = tid; i < 224 * 16; i += 256) {  // float2 over r
        int c = i >> 4, m = i & 15;
        int src;
        if (c < 64) src = 128 + c;
        else if (c < 128) src = 192 + (c - 64);
        else if (c < 192) src = 32 + (c - 128);
        else src = -1;
        float2 v;
        if (src >= 0) {
            v = *reinterpret_cast<const float2*>(A + src * RP + 2 * m);
        } else {
            int j = c - 192;
            int r = 2 * m;
            v.x = idn[(r >> 2) * DID + j];
            v.y = idn[((r + 1) >> 2) * DID + j];
        }
        *reinterpret_cast<float2*>(B + c * RP + 2 * m) = v;
    }
    __syncthreads();

    // ---- state MLP ----
    gemmT<4, 1, 224, 256>(B, sw1, sb1, C, 0);
    __syncthreads();
    gemmT<1, 2, 256, 64>(C, sw2, sb2, A, 96);  // tanh -> A rows [96:160]
    __syncthreads();

    // ---- h_new = decay*h + (1-decay)*tanh; write out + msg input ----
    for (int i = tid; i < ROWS * DD; i += 256) {
        int r = i >> 6, d = i & 63, ln = r >> 2, b = r & 3;
        float de = dec[r];
        float hn = de * A[(32 + d) * RP + r] + (1.0f - de) * A[(96 + d) * RP + r];
        g_h[((size_t)b * NN + n0 + ln) * DD + d] = hn;
        out[(((size_t)b * TT + t) * NN + n0 + ln) * DD + d] = hn;
        B[d * RP + r] = hn;
    }
    for (int i = tid; i < ROWS * DID; i += 256) {
        int r = i >> 5, j = i & 31;
        B[(64 + j) * RP + r] = idn[(r >> 2) * DID + j];
    }
    __syncthreads();

    // ---- msg MLP ----
    gemmT<4, 1, 96, 256>(B, mw1, mb1, C, 0);
    __syncthreads();
    gemmT<1, 2, 256, 64>(C, mw2, mb2, A, 0);  // tanh -> A rows [0:64]
    __syncthreads();
    for (int i = tid; i < ROWS * DD; i += 256) {
        int r = i >> 6, d = i & 63, ln = r >> 2, b = r & 3;
        g_msgs[p ^ 1][((size_t)b * NN + n0 + ln) * DD + d] = A[d * RP + r];
    }
}

__global__ void init_kernel(const float* __restrict__ h0, const float* __restrict__ m0,
                            const float* __restrict__ w0, const float* __restrict__ id0,
                            const float* __restrict__ dw2, const float* __restrict__ db2) {
    size_t i = (size_t)blockIdx.x * blockDim.x + threadIdx.x;
    if (i < (size_t)BSZ * NN * DD) {
        g_h[i] = h0[i];
        g_msgs[0][i] = m0[i];
    }
    if (i < (size_t)BSZ * NN * KK) g_wc[i] = w0[i];
    if (i < (size_t)NN * DID) g_ident[i] = id0[i];
    if (i < 256 * 128) {
        int r = (int)i >> 7, c = (int)i & 127;
        g_dw2p[i] = (c < 65) ? dw2[r * 65 + c] : 0.0f;
    }
    if (i < 128) g_db2p[i] = (i < 65) ? db2[i] : 0.0f;
}

#define SMEM_BYTES ((3 * 256 * RP + ROWS * KK + NT * DID + ROWS) * 4 + NT * KK * 4)

extern "C" void kernel_launch(void* const* d_in, const int* in_sizes, int n_in,
                              void* d_out, int out_size) {
    const float* cc   = (const float*)d_in[0];
    const float* h0   = (const float*)d_in[1];
    const float* m0   = (const float*)d_in[2];
    const float* w0   = (const float*)d_in[3];
    const float* hebb = (const float*)d_in[4];
    const float* id0  = (const float*)d_in[5];
    const float* sw1  = (const float*)d_in[6];
    const float* sb1  = (const float*)d_in[7];
    const float* sw2  = (const float*)d_in[8];
    const float* sb2  = (const float*)d_in[9];
    const float* mw1  = (const float*)d_in[10];
    const float* mb1  = (const float*)d_in[11];
    const float* mw2  = (const float*)d_in[12];
    const float* mb2  = (const float*)d_in[13];
    const float* dw1  = (const float*)d_in[14];
    const float* db1  = (const float*)d_in[15];
    const float* dw2  = (const float*)d_in[16];
    const float* db2  = (const float*)d_in[17];
    const int* conn   = (const int*)d_in[18];
    float* out = (float*)d_out;

    cudaFuncSetAttribute(step_kernel, cudaFuncAttributeMaxDynamicSharedMemorySize,
                         SMEM_BYTES);

    init_kernel<<<(BSZ * NN * DD + 255) / 256, 256>>>(h0, m0, w0, id0, dw2, db2);
    for (int t = 0; t < TT; t++) {
        step_kernel<<<NN / NT, 256, SMEM_BYTES>>>(
            cc, hebb, conn, sw1, sb1, sw2, sb2, mw1, mb1, mw2, mb2,
            dw1, db1, out, t, t & 1);
    }
}